// round 4
// baseline (speedup 1.0000x reference)
#include <cuda_runtime.h>
#include <cstdint>

#define DIM 256
#define NQ  8192
#define NE  8192
#define BM  64     // queries per block
#define BN  128    // codes per tile
#define BK  16     // k-slice
#define BNP 132    // padded Bs row stride (floats)

#define ZQ_ELEMS (NQ * DIM)

// ---------------- device scratch (referenced ONLY from device code) ----------------
__device__ float g_znorm[NQ * DIM];
__device__ float g_znorm2[NQ];
__device__ float g_enorm[NE * DIM];
__device__ float g_enorm2[NE];
__device__ int   g_idx[NQ];
__device__ float g_partial[1024];

// ---------------- f32x2 helpers (SASS FFMA2; PTX-only route) ----------------
__device__ __forceinline__ unsigned long long pack2(float x, float y) {
    unsigned long long r;
    asm("mov.b64 %0, {%1, %2};" : "=l"(r) : "f"(x), "f"(y));
    return r;
}
__device__ __forceinline__ void unpack2(unsigned long long v, float& x, float& y) {
    asm("mov.b64 {%0, %1}, %2;" : "=f"(x), "=f"(y) : "l"(v));
}
__device__ __forceinline__ void ffma2(unsigned long long& d, unsigned long long a,
                                      unsigned long long b) {
    asm("fma.rn.f32x2 %0, %1, %2, %0;" : "+l"(d) : "l"(a), "l"(b));
}

// ---------------- row L2 normalize: one warp per row ----------------
// is_code=1 -> write g_enorm / g_enorm2 ; is_code=0 -> g_znorm / g_znorm2.
__global__ void l2norm_rows(const float* __restrict__ in, int rows, int is_code) {
    int warp = (blockIdx.x * blockDim.x + threadIdx.x) >> 5;
    int lane = threadIdx.x & 31;
    if (warp >= rows) return;
    float* __restrict__ out = is_code ? g_enorm : g_znorm;
    const float4* src = (const float4*)(in + (size_t)warp * DIM);
    float4 v0 = src[lane];
    float4 v1 = src[lane + 32];
    float s = v0.x*v0.x + v0.y*v0.y + v0.z*v0.z + v0.w*v0.w
            + v1.x*v1.x + v1.y*v1.y + v1.z*v1.z + v1.w*v1.w;
    #pragma unroll
    for (int off = 16; off; off >>= 1) s += __shfl_xor_sync(0xffffffffu, s, off);
    float inv = 1.0f / fmaxf(sqrtf(s), 1e-12f);
    v0.x *= inv; v0.y *= inv; v0.z *= inv; v0.w *= inv;
    v1.x *= inv; v1.y *= inv; v1.z *= inv; v1.w *= inv;
    float4* dst = (float4*)(out + (size_t)warp * DIM);
    dst[lane]      = v0;
    dst[lane + 32] = v1;
    // sum of squares of the NORMALIZED vector, as the reference computes it
    float s2 = v0.x*v0.x + v0.y*v0.y + v0.z*v0.z + v0.w*v0.w
             + v1.x*v1.x + v1.y*v1.y + v1.z*v1.z + v1.w*v1.w;
    #pragma unroll
    for (int off = 16; off; off >>= 1) s2 += __shfl_xor_sync(0xffffffffu, s2, off);
    if (lane == 0) {
        if (is_code) g_enorm2[warp] = s2; else g_znorm2[warp] = s2;
    }
}

// ---------------- fused GEMM + argmin over d = (||z||^2 + ||e||^2) - 2 z.e ----
// Static smem only (~33 KB). Block: 64 queries x all codes (128-code tiles,
// k-sliced by 16, double buffered). Thread (tx,ty): rows ty*8.., cols tx*4..
__global__ __launch_bounds__(256)
void gemm_argmin() {
    __shared__ __align__(16) unsigned long long As2[2][BK][BM];   // dup pairs, 16 KB
    __shared__ __align__(16) float Bs[2][BK][BNP];                // ~16.9 KB

    int tid = threadIdx.x;
    int tx = tid & 31;
    int ty = tid >> 5;
    int qbase = blockIdx.x * BM;

    float4 ra, rb0, rb1;
    const int arow = tid >> 2;          // 0..63
    const int ak4  = (tid & 3) << 2;    // 0,4,8,12

    float rz2[8];
    #pragma unroll
    for (int i = 0; i < 8; i++) rz2[i] = g_znorm2[qbase + ty * 8 + i];

    float bestv[8];
    int   besti[8];
    #pragma unroll
    for (int i = 0; i < 8; i++) { bestv[i] = 3.4e38f; besti[i] = 0; }

    unsigned long long acc[8][2];

    const int NSTEP = (NE / BN) * (DIM / BK);   // 64 * 16 = 1024

    // prologue: step 0 into buffer 0
    {
        ra  = *(const float4*)&g_znorm[(size_t)(qbase + arow) * DIM + ak4];
        rb0 = *(const float4*)&g_enorm[(size_t)(0 + arow) * DIM + ak4];
        rb1 = *(const float4*)&g_enorm[(size_t)(64 + arow) * DIM + ak4];
        As2[0][ak4 + 0][arow] = pack2(ra.x, ra.x);
        As2[0][ak4 + 1][arow] = pack2(ra.y, ra.y);
        As2[0][ak4 + 2][arow] = pack2(ra.z, ra.z);
        As2[0][ak4 + 3][arow] = pack2(ra.w, ra.w);
        Bs[0][ak4 + 0][arow] = rb0.x;  Bs[0][ak4 + 0][arow + 64] = rb1.x;
        Bs[0][ak4 + 1][arow] = rb0.y;  Bs[0][ak4 + 1][arow + 64] = rb1.y;
        Bs[0][ak4 + 2][arow] = rb0.z;  Bs[0][ak4 + 2][arow + 64] = rb1.z;
        Bs[0][ak4 + 3][arow] = rb0.w;  Bs[0][ak4 + 3][arow + 64] = rb1.w;
    }
    __syncthreads();

    #pragma unroll 1
    for (int s = 0; s < NSTEP; s++) {
        int buf = s & 1;
        int kt  = s & 15;
        if (kt == 0) {
            #pragma unroll
            for (int i = 0; i < 8; i++) { acc[i][0] = 0ull; acc[i][1] = 0ull; }
        }
        if (s + 1 < NSTEP) {
            int ns = s + 1;
            int ct = ns >> 4;
            int kb = (ns & 15) * BK;
            ra  = *(const float4*)&g_znorm[(size_t)(qbase + arow) * DIM + kb + ak4];
            rb0 = *(const float4*)&g_enorm[(size_t)(ct * BN + arow) * DIM + kb + ak4];
            rb1 = *(const float4*)&g_enorm[(size_t)(ct * BN + 64 + arow) * DIM + kb + ak4];
        }

        #pragma unroll
        for (int kk = 0; kk < BK; kk++) {
            ulonglong2 a01 = *(const ulonglong2*)&As2[buf][kk][ty * 8 + 0];
            ulonglong2 a23 = *(const ulonglong2*)&As2[buf][kk][ty * 8 + 2];
            ulonglong2 a45 = *(const ulonglong2*)&As2[buf][kk][ty * 8 + 4];
            ulonglong2 a67 = *(const ulonglong2*)&As2[buf][kk][ty * 8 + 6];
            ulonglong2 b   = *(const ulonglong2*)&Bs[buf][kk][tx * 4];
            ffma2(acc[0][0], a01.x, b.x); ffma2(acc[0][1], a01.x, b.y);
            ffma2(acc[1][0], a01.y, b.x); ffma2(acc[1][1], a01.y, b.y);
            ffma2(acc[2][0], a23.x, b.x); ffma2(acc[2][1], a23.x, b.y);
            ffma2(acc[3][0], a23.y, b.x); ffma2(acc[3][1], a23.y, b.y);
            ffma2(acc[4][0], a45.x, b.x); ffma2(acc[4][1], a45.x, b.y);
            ffma2(acc[5][0], a45.y, b.x); ffma2(acc[5][1], a45.y, b.y);
            ffma2(acc[6][0], a67.x, b.x); ffma2(acc[6][1], a67.x, b.y);
            ffma2(acc[7][0], a67.y, b.x); ffma2(acc[7][1], a67.y, b.y);
        }

        if (s + 1 < NSTEP) {
            int nb = (s + 1) & 1;
            As2[nb][ak4 + 0][arow] = pack2(ra.x, ra.x);
            As2[nb][ak4 + 1][arow] = pack2(ra.y, ra.y);
            As2[nb][ak4 + 2][arow] = pack2(ra.z, ra.z);
            As2[nb][ak4 + 3][arow] = pack2(ra.w, ra.w);
            Bs[nb][ak4 + 0][arow] = rb0.x;  Bs[nb][ak4 + 0][arow + 64] = rb1.x;
            Bs[nb][ak4 + 1][arow] = rb0.y;  Bs[nb][ak4 + 1][arow + 64] = rb1.y;
            Bs[nb][ak4 + 2][arow] = rb0.z;  Bs[nb][ak4 + 2][arow + 64] = rb1.z;
            Bs[nb][ak4 + 3][arow] = rb0.w;  Bs[nb][ak4 + 3][arow + 64] = rb1.w;
        }
        __syncthreads();

        if (kt == 15) {   // finished K for this 128-code tile: running argmin
            int colbase = (s >> 4) * BN + tx * 4;
            float4 e2 = *(const float4*)(g_enorm2 + colbase);
            #pragma unroll
            for (int i = 0; i < 8; i++) {
                float c0, c1, c2, c3;
                unpack2(acc[i][0], c0, c1);
                unpack2(acc[i][1], c2, c3);
                // key = (z2 + e2) - 2*dot, contraction-free like the reference
                float k0 = __fsub_rn(__fadd_rn(rz2[i], e2.x), __fmul_rn(2.0f, c0));
                float k1 = __fsub_rn(__fadd_rn(rz2[i], e2.y), __fmul_rn(2.0f, c1));
                float k2 = __fsub_rn(__fadd_rn(rz2[i], e2.z), __fmul_rn(2.0f, c2));
                float k3 = __fsub_rn(__fadd_rn(rz2[i], e2.w), __fmul_rn(2.0f, c3));
                if (k0 < bestv[i]) { bestv[i] = k0; besti[i] = colbase; }
                if (k1 < bestv[i]) { bestv[i] = k1; besti[i] = colbase + 1; }
                if (k2 < bestv[i]) { bestv[i] = k2; besti[i] = colbase + 2; }
                if (k3 < bestv[i]) { bestv[i] = k3; besti[i] = colbase + 3; }
            }
        }
    }

    // Cross-thread argmin reduction per row (reuse smem); ties -> smallest index
    float* sval = (float*)&As2[0][0][0];    // 64*32 floats = 8 KB
    int*   sidx = (int*)&Bs[0][0][0];       // 64*32 ints  = 8 KB
    #pragma unroll
    for (int i = 0; i < 8; i++) {
        sval[(ty * 8 + i) * 32 + tx] = bestv[i];
        sidx[(ty * 8 + i) * 32 + tx] = besti[i];
    }
    __syncthreads();
    if (tid < BM) {
        float bv = 3.4e38f;
        int bi = 0x7fffffff;
        #pragma unroll 4
        for (int t = 0; t < 32; t++) {
            float v = sval[tid * 32 + t];
            int ix = sidx[tid * 32 + t];
            if (v < bv || (v == bv && ix < bi)) { bv = v; bi = ix; }
        }
        g_idx[qbase + tid] = bi;
    }
}

// ---------------- gather z_q, per-block loss partials, index output ----------------
__global__ void gather_loss(float* __restrict__ zq_out, float* __restrict__ idxf_out,
                            int write_zq) {
    __shared__ float wsum[8];
    int tid = threadIdx.x;
    int lane = tid & 31;
    int w = tid >> 5;
    int row = blockIdx.x * 8 + w;

    int e = g_idx[row] & (NE - 1);   // defensive clamp: never OOB
    const float4* ev = (const float4*)(g_enorm + (size_t)e * DIM);
    const float4* zv = (const float4*)(g_znorm + (size_t)row * DIM);
    float4 a0 = ev[lane], a1 = ev[lane + 32];
    float4 b0 = zv[lane], b1 = zv[lane + 32];

    if (write_zq) {
        float4* o = (float4*)(zq_out + (size_t)row * DIM);
        o[lane]      = a0;
        o[lane + 32] = a1;
    }
    float dx, s = 0.f;
    dx = a0.x - b0.x; s += dx * dx;  dx = a0.y - b0.y; s += dx * dx;
    dx = a0.z - b0.z; s += dx * dx;  dx = a0.w - b0.w; s += dx * dx;
    dx = a1.x - b1.x; s += dx * dx;  dx = a1.y - b1.y; s += dx * dx;
    dx = a1.z - b1.z; s += dx * dx;  dx = a1.w - b1.w; s += dx * dx;
    #pragma unroll
    for (int off = 16; off; off >>= 1) s += __shfl_xor_sync(0xffffffffu, s, off);
    if (lane == 0) {
        wsum[w] = s;
        if (idxf_out) idxf_out[row] = (float)e;
    }
    __syncthreads();
    if (tid == 0) {
        float t = 0.f;
        #pragma unroll
        for (int i = 0; i < 8; i++) t += wsum[i];
        g_partial[blockIdx.x] = t;
    }
}

// ---------------- deterministic loss finalize ----------------
__global__ void finalize_loss(float* __restrict__ loss_out) {
    __shared__ float sh[256];
    int tid = threadIdx.x;
    float s = 0.f;
    for (int i = tid; i < 1024; i += 256) s += g_partial[i];
    sh[tid] = s;
    __syncthreads();
    for (int off = 128; off; off >>= 1) {
        if (tid < off) sh[tid] += sh[tid + off];
        __syncthreads();
    }
    if (tid == 0 && loss_out) {
        // loss = (BETA + 1) * mean((z_q - z)^2), BETA = 0.25
        loss_out[0] = 1.25f * sh[0] / (float)ZQ_ELEMS;
    }
}

// ---------------- launch (NO __device__ symbols may appear below) ----------------
extern "C" void kernel_launch(void* const* d_in, const int* in_sizes, int n_in,
                              void* d_out, int out_size) {
    const float* z  = (const float*)d_in[0];          // [8,1024,256] fp32
    const float* ew = (const float*)d_in[1];          // [8192,256]  fp32
    float* out = (float*)d_out;

    // Output layout dispatch (reference returns (z_q, loss, indices)):
    //   R = out_size - 2097152:  R>=NQ+1 -> [z_q|loss|idx], R==NQ -> [z_q|idx],
    //   R>=1 -> [z_q|loss], R==0 -> [z_q]. Degenerate: NQ -> idx only, 1 -> loss only.
    int   write_zq = 0;
    float* lossp = nullptr;
    float* idxf  = nullptr;
    if (out_size >= ZQ_ELEMS) {
        write_zq = 1;
        long R = (long)out_size - (long)ZQ_ELEMS;
        if (R >= (long)NQ + 1)      { lossp = out + ZQ_ELEMS; idxf = out + ZQ_ELEMS + 1; }
        else if (R == (long)NQ)     { idxf = out + ZQ_ELEMS; }
        else if (R >= 1)            { lossp = out + ZQ_ELEMS; }
    } else if (out_size == NQ) {
        idxf = out;
    } else if (out_size == 1) {
        lossp = out;
    }

    l2norm_rows<<<NE / 8, 256>>>(ew, NE, 1);
    l2norm_rows<<<NQ / 8, 256>>>(z, NQ, 0);
    gemm_argmin<<<NQ / BM, 256>>>();
    gather_loss<<<NQ / 8, 256>>>(out, idxf, write_zq);
    finalize_loss<<<1, 256>>>(lossp);
}